// round 3
// baseline (speedup 1.0000x reference)
#include <cuda_runtime.h>
#include <stdint.h>
#include <math.h>

#define B_ 2
#define S_ 2048
#define E_ 1024
#define H_ 16
#define D_ 64
#define BH_ (B_*H_)

__device__ float g_Q[(size_t)BH_ * S_ * D_];
__device__ float g_K[(size_t)BH_ * S_ * D_];
__device__ float g_V[(size_t)BH_ * S_ * D_];
__device__ float g_C[(size_t)BH_ * S_ * D_];

// ---------------- 3xTF32 helpers ----------------
__device__ __forceinline__ uint32_t f2tf(float x) {
    uint32_t r;
    asm("cvt.rna.tf32.f32 %0, %1;" : "=r"(r) : "f"(x));
    return r;
}
__device__ __forceinline__ void split_tf(float x, uint32_t& hi, uint32_t& lo) {
    hi = f2tf(x);
    lo = f2tf(x - __uint_as_float(hi));
}
__device__ __forceinline__ void mma8(float* c,
                                     uint32_t a0, uint32_t a1, uint32_t a2, uint32_t a3,
                                     uint32_t b0, uint32_t b1) {
    asm volatile(
        "mma.sync.aligned.m16n8k8.row.col.f32.tf32.tf32.f32 "
        "{%0,%1,%2,%3}, {%4,%5,%6,%7}, {%8,%9}, {%0,%1,%2,%3};\n"
        : "+f"(c[0]), "+f"(c[1]), "+f"(c[2]), "+f"(c[3])
        : "r"(a0), "r"(a1), "r"(a2), "r"(a3), "r"(b0), "r"(b1));
}

// fast exp on FMA pipe; valid for x <= 0 (clamped below ~-69 in exponent room)
__device__ __forceinline__ float fast_exp(float x) {
    float t = x * 1.44269504089f;
    t = fmaxf(t, -100.0f);
    float rm = t + 12582912.0f;               // round to nearest int (magic)
    int ib = __float_as_int(rm) - 0x4B400000;
    float f = t - (rm - 12582912.0f);         // frac in [-0.5,0.5]
    float p = 0.0013333558f;
    p = fmaf(p, f, 0.0096181291f);
    p = fmaf(p, f, 0.0555041087f);
    p = fmaf(p, f, 0.2402265069f);
    p = fmaf(p, f, 0.6931471806f);
    p = fmaf(p, f, 1.0f);
    return __int_as_float(__float_as_int(p) + (ib << 23));
}

// packed-uint4 split stores for K (B-operand of QK) and V (B-operand of PV)
__device__ __forceinline__ void storeK(uint32_t* Kp, int slot, float4 f) {
    int key = slot >> 4, c4 = (slot & 15) * 4;
    int k8 = c4 >> 3, w = (c4 >> 2) & 1;
    const float* fe = (const float*)&f;
#pragma unroll
    for (int j = 0; j < 4; j++) {
        uint32_t hi, lo; split_tf(fe[j], hi, lo);
        int idx = (((k8 * 64 + key) * 4 + j) << 2) + w;
        Kp[idx] = hi; Kp[idx + 2] = lo;
    }
}
__device__ __forceinline__ void storeV(uint32_t* Vp, int slot, float4 f) {
    int key = slot >> 4, c4 = (slot & 15) * 4;
    int kk8 = key >> 3, tg = key & 3, w = (key >> 2) & 1;
    const float* fe = (const float*)&f;
#pragma unroll
    for (int j = 0; j < 4; j++) {
        uint32_t hi, lo; split_tf(fe[j], hi, lo);
        int idx = (((kk8 * 64 + (c4 + j)) * 4 + tg) << 2) + w;
        Vp[idx] = hi; Vp[idx + 2] = lo;
    }
}

// ---------------------------------------------------------------------------
// QKV projection (FFMA, unchanged from round-1 passing kernel)
// ---------------------------------------------------------------------------
__global__ __launch_bounds__(256) void proj_kernel(
    const float* __restrict__ q, const float* __restrict__ k, const float* __restrict__ v,
    const float* __restrict__ Wq, const float* __restrict__ Wk, const float* __restrict__ Wv,
    const float* __restrict__ bq, const float* __restrict__ bk, const float* __restrict__ bv)
{
    __shared__ float As[16][132];
    __shared__ float Bs[16][64];

    const int z = blockIdx.z;
    const float* X    = (z == 0) ? q  : (z == 1) ? k  : v;
    const float* W    = (z == 0) ? Wq : (z == 1) ? Wk : Wv;
    const float* bias = (z == 0) ? bq : (z == 1) ? bk : bv;
    float* Out        = (z == 0) ? g_Q : (z == 1) ? g_K : g_V;

    const int bh = blockIdx.y;
    const int b = bh >> 4;
    const int h = bh & 15;
    const int s0 = blockIdx.x * 128;
    const int tid = threadIdx.x;
    const int ng = tid & 15;
    const int mg = tid >> 4;

    const float* Xb = X + ((size_t)b * S_ + s0) * E_;
    const float* Wh = W + (size_t)h * E_ * D_;

    float acc[8][4];
#pragma unroll
    for (int i = 0; i < 8; i++)
#pragma unroll
        for (int j = 0; j < 4; j++) acc[i][j] = 0.f;

    for (int k0 = 0; k0 < E_; k0 += 16) {
#pragma unroll
        for (int it = 0; it < 2; it++) {
            int i = tid + it * 256;
            int row = i >> 2;
            int c4 = (i & 3) * 4;
            float4 f = *(const float4*)(Xb + (size_t)row * E_ + k0 + c4);
            As[c4 + 0][row] = f.x; As[c4 + 1][row] = f.y;
            As[c4 + 2][row] = f.z; As[c4 + 3][row] = f.w;
        }
        {
            int r = tid >> 4, c4 = (tid & 15) * 4;
            *(float4*)&Bs[r][c4] = *(const float4*)(Wh + (size_t)(k0 + r) * D_ + c4);
        }
        __syncthreads();
#pragma unroll
        for (int kk = 0; kk < 16; kk++) {
            float4 a0 = *(float4*)&As[kk][mg * 8];
            float4 a1 = *(float4*)&As[kk][mg * 8 + 4];
            float4 b4 = *(float4*)&Bs[kk][ng * 4];
            float a[8] = {a0.x, a0.y, a0.z, a0.w, a1.x, a1.y, a1.z, a1.w};
            float bb[4] = {b4.x, b4.y, b4.z, b4.w};
#pragma unroll
            for (int i = 0; i < 8; i++)
#pragma unroll
                for (int j = 0; j < 4; j++) acc[i][j] += a[i] * bb[j];
        }
        __syncthreads();
    }

    float4 bias4 = *(const float4*)(bias + h * D_ + ng * 4);
    float* Ob = Out + ((size_t)bh * S_ + s0 + mg * 8) * D_ + ng * 4;
#pragma unroll
    for (int i = 0; i < 8; i++) {
        float4 r;
        r.x = acc[i][0] + bias4.x; r.y = acc[i][1] + bias4.y;
        r.z = acc[i][2] + bias4.z; r.w = acc[i][3] + bias4.w;
        *(float4*)(Ob + (size_t)i * D_) = r;
    }
}

// ---------------------------------------------------------------------------
// Flash attention, 3xTF32 mma.sync. BM=128, BN=64, 128 thr (4 warps, m32xn64).
// Packed smem (uint4 {hi_k, hi_k+4, lo_k, lo_k+4}); 192KB dynamic smem.
// grid = (S/128, BH)
// ---------------------------------------------------------------------------
#define ATT_SMEM (12288 * 16)

__global__ __launch_bounds__(128) void attn_kernel()
{
    extern __shared__ uint4 sm4[];
    uint32_t* Qp = (uint32_t*)(sm4);          // [k8=8][row=128][tg=4] uint4
    uint32_t* Kp = (uint32_t*)(sm4 + 4096);   // [k8=8][key=64][tg=4]
    uint32_t* Vp = (uint32_t*)(sm4 + 6144);   // [kk8=8][d=64][tg=4]
    uint32_t* Pp = (uint32_t*)(sm4 + 8192);   // [kk8=8][row=128][tg=4]
    const uint4* Q4 = sm4;
    const uint4* K4 = sm4 + 4096;
    const uint4* V4 = sm4 + 6144;
    const uint4* P4 = sm4 + 8192;

    const int bh = blockIdx.y;
    const int q0 = blockIdx.x * 128;
    const int tid = threadIdx.x;
    const int lane = tid & 31;
    const int warp = tid >> 5;
    const int g = lane >> 2;
    const int tg = lane & 3;
    const int r0 = warp * 32 + g;

    const float* Qg = g_Q + ((size_t)bh * S_ + q0) * D_;
    const float* Kg = g_K + (size_t)bh * S_ * D_;
    const float* Vg = g_V + (size_t)bh * S_ * D_;

    // ---- load + split Q tile (once), prescaled by 1/8 ----
#pragma unroll
    for (int it = 0; it < 16; it++) {
        int slot = tid + it * 128;            // 0..2047
        int row = slot >> 4;
        int c4 = (slot & 15) * 4;
        float4 f = *(const float4*)(Qg + (size_t)row * D_ + c4);
        int k8 = c4 >> 3, w = (c4 >> 2) & 1;
        const float* fe = (const float*)&f;
#pragma unroll
        for (int j = 0; j < 4; j++) {
            uint32_t hi, lo; split_tf(fe[j] * 0.125f, hi, lo);
            int idx = (((k8 * 128 + row) * 4 + j) << 2) + w;
            Qp[idx] = hi; Qp[idx + 2] = lo;
        }
    }

    // ---- preload stage 0 of K, V ----
#pragma unroll
    for (int it = 0; it < 8; it++) {
        int slot = tid + it * 128;            // 0..1023
        storeK(Kp, slot, *(const float4*)(Kg + (size_t)(slot >> 4) * D_ + (slot & 15) * 4));
        storeV(Vp, slot, *(const float4*)(Vg + (size_t)(slot >> 4) * D_ + (slot & 15) * 4));
    }
    __syncthreads();

    float m_i[4], l_i[4], oacc[2][8][4];
#pragma unroll
    for (int r = 0; r < 4; r++) { m_i[r] = -1e30f; l_i[r] = 0.f; }
#pragma unroll
    for (int f = 0; f < 2; f++)
#pragma unroll
        for (int nf = 0; nf < 8; nf++)
#pragma unroll
            for (int c = 0; c < 4; c++) oacc[f][nf][c] = 0.f;

    for (int kb = 0; kb < 32; kb++) {
        // ---- S = (Q/8) K^T ----
        float sacc[2][8][4];
#pragma unroll
        for (int f = 0; f < 2; f++)
#pragma unroll
            for (int nf = 0; nf < 8; nf++)
#pragma unroll
                for (int c = 0; c < 4; c++) sacc[f][nf][c] = 0.f;

#pragma unroll 2
        for (int k8 = 0; k8 < 8; k8++) {
            const uint4* Qb = Q4 + (size_t)(k8 * 128 + r0) * 4 + tg;
            uint4 A0 = Qb[0], A1 = Qb[32], A2 = Qb[64], A3 = Qb[96];
            uint4 Bf[8];
#pragma unroll
            for (int nf = 0; nf < 8; nf++) Bf[nf] = K4[(size_t)(k8 * 64 + nf * 8 + g) * 4 + tg];
#pragma unroll
            for (int nf = 0; nf < 8; nf++) mma8(sacc[0][nf], A0.x, A1.x, A0.y, A1.y, Bf[nf].x, Bf[nf].y);
#pragma unroll
            for (int nf = 0; nf < 8; nf++) mma8(sacc[1][nf], A2.x, A3.x, A2.y, A3.y, Bf[nf].x, Bf[nf].y);
#pragma unroll
            for (int nf = 0; nf < 8; nf++) mma8(sacc[0][nf], A0.z, A1.z, A0.w, A1.w, Bf[nf].x, Bf[nf].y);
#pragma unroll
            for (int nf = 0; nf < 8; nf++) mma8(sacc[1][nf], A2.z, A3.z, A2.w, A3.w, Bf[nf].x, Bf[nf].y);
#pragma unroll
            for (int nf = 0; nf < 8; nf++) mma8(sacc[0][nf], A0.x, A1.x, A0.y, A1.y, Bf[nf].z, Bf[nf].w);
#pragma unroll
            for (int nf = 0; nf < 8; nf++) mma8(sacc[1][nf], A2.x, A3.x, A2.y, A3.y, Bf[nf].z, Bf[nf].w);
        }

        // prefetch next K into registers (covered by softmax latency)
        float4 kreg[8];
        if (kb < 31) {
#pragma unroll
            for (int it = 0; it < 8; it++) {
                int slot = tid + it * 128;
                kreg[it] = *(const float4*)(Kg + ((size_t)(kb + 1) * 64 + (slot >> 4)) * D_ + (slot & 15) * 4);
            }
        }

        // ---- online softmax + stage split P ----
#pragma unroll
        for (int r = 0; r < 4; r++) {
            int f = r >> 1, cb = (r & 1) * 2;
            float mx = -1e30f;
#pragma unroll
            for (int nf = 0; nf < 8; nf++)
                mx = fmaxf(mx, fmaxf(sacc[f][nf][cb], sacc[f][nf][cb + 1]));
            mx = fmaxf(mx, __shfl_xor_sync(0xffffffffu, mx, 1));
            mx = fmaxf(mx, __shfl_xor_sync(0xffffffffu, mx, 2));
            float mn = fmaxf(m_i[r], mx);
            float corr = fast_exp(m_i[r] - mn);
            m_i[r] = mn;
            int rowIdx = warp * 32 + f * 16 + g + (r & 1) * 8;
            float sum = 0.f;
#pragma unroll
            for (int nf = 0; nf < 8; nf++) {
#pragma unroll
                for (int cc = 0; cc < 2; cc++) {
                    float p = fast_exp(sacc[f][nf][cb + cc] - mn);
                    sum += p;
                    uint32_t hi, lo; split_tf(p, hi, lo);
                    int t2 = 2 * tg + cc;
                    int idx = (((nf * 128 + rowIdx) * 4 + (t2 & 3)) << 2) + (t2 >> 2);
                    Pp[idx] = hi; Pp[idx + 2] = lo;
                }
                oacc[f][nf][cb] *= corr;
                oacc[f][nf][cb + 1] *= corr;
            }
            sum += __shfl_xor_sync(0xffffffffu, sum, 1);
            sum += __shfl_xor_sync(0xffffffffu, sum, 2);
            l_i[r] = l_i[r] * corr + sum;
        }
        __syncthreads();              // P visible; Kp reads done

        if (kb < 31) {
#pragma unroll
            for (int it = 0; it < 8; it++) storeK(Kp, tid + it * 128, kreg[it]);
        }
        float4 vreg[8];
        if (kb < 31) {
#pragma unroll
            for (int it = 0; it < 8; it++) {
                int slot = tid + it * 128;
                vreg[it] = *(const float4*)(Vg + ((size_t)(kb + 1) * 64 + (slot >> 4)) * D_ + (slot & 15) * 4);
            }
        }

        // ---- O += P V ----
#pragma unroll 2
        for (int kk8 = 0; kk8 < 8; kk8++) {
            const uint4* Pb = P4 + (size_t)(kk8 * 128 + r0) * 4 + tg;
            uint4 A0 = Pb[0], A1 = Pb[32], A2 = Pb[64], A3 = Pb[96];
            uint4 Bf[8];
#pragma unroll
            for (int nf = 0; nf < 8; nf++) Bf[nf] = V4[(size_t)(kk8 * 64 + nf * 8 + g) * 4 + tg];
#pragma unroll
            for (int nf = 0; nf < 8; nf++) mma8(oacc[0][nf], A0.x, A1.x, A0.y, A1.y, Bf[nf].x, Bf[nf].y);
#pragma unroll
            for (int nf = 0; nf < 8; nf++) mma8(oacc[1][nf], A2.x, A3.x, A2.y, A3.y, Bf[nf].x, Bf[nf].y);
#pragma unroll
            for (int nf = 0; nf < 8; nf++) mma8(oacc[0][nf], A0.z, A1.z, A0.w, A1.w, Bf[nf].x, Bf[nf].y);
#pragma unroll
            for (int nf = 0; nf < 8; nf++) mma8(oacc[1][nf], A2.z, A3.z, A2.w, A3.w, Bf[nf].x, Bf[nf].y);
#pragma unroll
            for (int nf = 0; nf < 8; nf++) mma8(oacc[0][nf], A0.x, A1.x, A0.y, A1.y, Bf[nf].z, Bf[nf].w);
#pragma unroll
            for (int nf = 0; nf < 8; nf++) mma8(oacc[1][nf], A2.x, A3.x, A2.y, A3.y, Bf[nf].z, Bf[nf].w);
        }
        __syncthreads();              // Vp/Pp reads done

        if (kb < 31) {
#pragma unroll
            for (int it = 0; it < 8; it++) storeV(Vp, tid + it * 128, vreg[it]);
        }
    }

    // ---- epilogue: normalize, write ctx ----
    float* Cg = g_C + (size_t)bh * S_ * D_;
#pragma unroll
    for (int f = 0; f < 2; f++) {
#pragma unroll
        for (int rr = 0; rr < 2; rr++) {
            float inv = 1.f / l_i[f * 2 + rr];
            int row = q0 + warp * 32 + f * 16 + g + rr * 8;
#pragma unroll
            for (int nf = 0; nf < 8; nf++) {
                float2 v = make_float2(oacc[f][nf][rr * 2] * inv, oacc[f][nf][rr * 2 + 1] * inv);
                *(float2*)(Cg + (size_t)row * D_ + nf * 8 + 2 * tg) = v;
            }
        }
    }
}

// ---------------------------------------------------------------------------
// Output projection (FFMA, unchanged)
// ---------------------------------------------------------------------------
__global__ __launch_bounds__(256) void oproj_kernel(
    const float* __restrict__ Wo, const float* __restrict__ bo, float* __restrict__ out)
{
    __shared__ float As[16][132];
    __shared__ float Bs[16][64];

    const int m0 = blockIdx.x * 128;
    const int n0 = blockIdx.y * 64;
    const int tid = threadIdx.x;
    const int ng = tid & 15;
    const int mg = tid >> 4;
    const int b = m0 >> 11;
    const int sbase = m0 & (S_ - 1);

    float acc[8][4];
#pragma unroll
    for (int i = 0; i < 8; i++)
#pragma unroll
        for (int j = 0; j < 4; j++) acc[i][j] = 0.f;

    for (int k0 = 0; k0 < E_; k0 += 16) {
#pragma unroll
        for (int it = 0; it < 2; it++) {
            int i = tid + it * 256;
            int row = i >> 2;
            int c4 = (i & 3) * 4;
            int e = k0 + c4;
            int h = e >> 6;
            int dd = e & 63;
            float4 f = *(const float4*)(g_C +
                (((size_t)(b * H_ + h) * S_ + sbase + row) * D_ + dd));
            As[c4 + 0][row] = f.x; As[c4 + 1][row] = f.y;
            As[c4 + 2][row] = f.z; As[c4 + 3][row] = f.w;
        }
        {
            int r = tid >> 4, c4 = (tid & 15) * 4;
            *(float4*)&Bs[r][c4] = *(const float4*)(Wo + (size_t)(k0 + r) * E_ + n0 + c4);
        }
        __syncthreads();
#pragma unroll
        for (int kk = 0; kk < 16; kk++) {
            float4 a0 = *(float4*)&As[kk][mg * 8];
            float4 a1 = *(float4*)&As[kk][mg * 8 + 4];
            float4 b4 = *(float4*)&Bs[kk][ng * 4];
            float a[8] = {a0.x, a0.y, a0.z, a0.w, a1.x, a1.y, a1.z, a1.w};
            float bb[4] = {b4.x, b4.y, b4.z, b4.w};
#pragma unroll
            for (int i = 0; i < 8; i++)
#pragma unroll
                for (int j = 0; j < 4; j++) acc[i][j] += a[i] * bb[j];
        }
        __syncthreads();
    }

    float4 b4 = *(const float4*)(bo + n0 + ng * 4);
#pragma unroll
    for (int i = 0; i < 8; i++) {
        size_t row = (size_t)m0 + mg * 8 + i;
        float4 r;
        r.x = acc[i][0] + b4.x; r.y = acc[i][1] + b4.y;
        r.z = acc[i][2] + b4.z; r.w = acc[i][3] + b4.w;
        *(float4*)(out + row * E_ + n0 + ng * 4) = r;
    }
}

// ---------------------------------------------------------------------------
extern "C" void kernel_launch(void* const* d_in, const int* in_sizes, int n_in,
                              void* d_out, int out_size)
{
    const float* q  = (const float*)d_in[0];
    const float* k  = (const float*)d_in[1];
    const float* v  = (const float*)d_in[2];
    const float* Wq = (const float*)d_in[3];
    const float* Wk = (const float*)d_in[4];
    const float* Wv = (const float*)d_in[5];
    const float* bq = (const float*)d_in[6];
    const float* bk = (const float*)d_in[7];
    const float* bv = (const float*)d_in[8];
    const float* Wo = (const float*)d_in[9];
    const float* bo = (const float*)d_in[10];
    float* out = (float*)d_out;

    cudaFuncSetAttribute(attn_kernel, cudaFuncAttributeMaxDynamicSharedMemorySize, ATT_SMEM);

    proj_kernel<<<dim3(S_ / 128, BH_, 3), 256>>>(q, k, v, Wq, Wk, Wv, bq, bk, bv);
    attn_kernel<<<dim3(S_ / 128, BH_), 128, ATT_SMEM>>>();
    oproj_kernel<<<dim3((B_ * S_) / 128, E_ / 64), 256>>>(Wo, bo, out);
}

// round 5
// speedup vs baseline: 1.4025x; 1.4025x over previous
#include <cuda_runtime.h>
#include <stdint.h>
#include <math.h>

#define B_ 2
#define S_ 2048
#define E_ 1024
#define H_ 16
#define D_ 64
#define BH_ (B_*H_)

__device__ float g_Q[(size_t)BH_ * S_ * D_];
__device__ float g_K[(size_t)BH_ * S_ * D_];
__device__ float g_V[(size_t)BH_ * S_ * D_];
__device__ float g_C[(size_t)BH_ * S_ * D_];

// ---------------- tf32 helpers ----------------
__device__ __forceinline__ uint32_t f2tf(float x) {
    uint32_t r;
    asm("cvt.rna.tf32.f32 %0, %1;" : "=r"(r) : "f"(x));
    return r;
}
__device__ __forceinline__ void split_tf(float x, uint32_t& hi, uint32_t& lo) {
    hi = f2tf(x);
    lo = f2tf(x - __uint_as_float(hi));
}
__device__ __forceinline__ void mma8(float* c,
                                     uint32_t a0, uint32_t a1, uint32_t a2, uint32_t a3,
                                     uint32_t b0, uint32_t b1) {
    asm volatile(
        "mma.sync.aligned.m16n8k8.row.col.f32.tf32.tf32.f32 "
        "{%0,%1,%2,%3}, {%4,%5,%6,%7}, {%8,%9}, {%0,%1,%2,%3};\n"
        : "+f"(c[0]), "+f"(c[1]), "+f"(c[2]), "+f"(c[3])
        : "r"(a0), "r"(a1), "r"(a2), "r"(a3), "r"(b0), "r"(b1));
}

// fast exp on FMA pipe; args <= 0
__device__ __forceinline__ float fast_exp(float x) {
    float t = x * 1.44269504089f;
    t = fmaxf(t, -100.0f);
    float rm = t + 12582912.0f;
    int ib = __float_as_int(rm) - 0x4B400000;
    float f = t - (rm - 12582912.0f);
    float p = 0.0013333558f;
    p = fmaf(p, f, 0.0096181291f);
    p = fmaf(p, f, 0.0555041087f);
    p = fmaf(p, f, 0.2402265069f);
    p = fmaf(p, f, 0.6931471806f);
    p = fmaf(p, f, 1.0f);
    return __int_as_float(__float_as_int(p) + (ib << 23));
}

// ---------------------------------------------------------------------------
// QKV projection (FFMA, unchanged — known good)
// ---------------------------------------------------------------------------
__global__ __launch_bounds__(256) void proj_kernel(
    const float* __restrict__ q, const float* __restrict__ k, const float* __restrict__ v,
    const float* __restrict__ Wq, const float* __restrict__ Wk, const float* __restrict__ Wv,
    const float* __restrict__ bq, const float* __restrict__ bk, const float* __restrict__ bv)
{
    __shared__ float As[16][132];
    __shared__ float Bs[16][64];

    const int z = blockIdx.z;
    const float* X    = (z == 0) ? q  : (z == 1) ? k  : v;
    const float* W    = (z == 0) ? Wq : (z == 1) ? Wk : Wv;
    const float* bias = (z == 0) ? bq : (z == 1) ? bk : bv;
    float* Out        = (z == 0) ? g_Q : (z == 1) ? g_K : g_V;

    const int bh = blockIdx.y;
    const int b = bh >> 4;
    const int h = bh & 15;
    const int s0 = blockIdx.x * 128;
    const int tid = threadIdx.x;
    const int ng = tid & 15;
    const int mg = tid >> 4;

    const float* Xb = X + ((size_t)b * S_ + s0) * E_;
    const float* Wh = W + (size_t)h * E_ * D_;

    float acc[8][4];
#pragma unroll
    for (int i = 0; i < 8; i++)
#pragma unroll
        for (int j = 0; j < 4; j++) acc[i][j] = 0.f;

    for (int k0 = 0; k0 < E_; k0 += 16) {
#pragma unroll
        for (int it = 0; it < 2; it++) {
            int i = tid + it * 256;
            int row = i >> 2;
            int c4 = (i & 3) * 4;
            float4 f = *(const float4*)(Xb + (size_t)row * E_ + k0 + c4);
            As[c4 + 0][row] = f.x; As[c4 + 1][row] = f.y;
            As[c4 + 2][row] = f.z; As[c4 + 3][row] = f.w;
        }
        {
            int r = tid >> 4, c4 = (tid & 15) * 4;
            *(float4*)&Bs[r][c4] = *(const float4*)(Wh + (size_t)(k0 + r) * D_ + c4);
        }
        __syncthreads();
#pragma unroll
        for (int kk = 0; kk < 16; kk++) {
            float4 a0 = *(float4*)&As[kk][mg * 8];
            float4 a1 = *(float4*)&As[kk][mg * 8 + 4];
            float4 b4 = *(float4*)&Bs[kk][ng * 4];
            float a[8] = {a0.x, a0.y, a0.z, a0.w, a1.x, a1.y, a1.z, a1.w};
            float bb[4] = {b4.x, b4.y, b4.z, b4.w};
#pragma unroll
            for (int i = 0; i < 8; i++)
#pragma unroll
                for (int j = 0; j < 4; j++) acc[i][j] += a[i] * bb[j];
        }
        __syncthreads();
    }

    float4 bias4 = *(const float4*)(bias + h * D_ + ng * 4);
    float* Ob = Out + ((size_t)bh * S_ + s0 + mg * 8) * D_ + ng * 4;
#pragma unroll
    for (int i = 0; i < 8; i++) {
        float4 r;
        r.x = acc[i][0] + bias4.x; r.y = acc[i][1] + bias4.y;
        r.z = acc[i][2] + bias4.z; r.w = acc[i][3] + bias4.w;
        *(float4*)(Ob + (size_t)i * D_) = r;
    }
}

// ---------------------------------------------------------------------------
// Flash attention: tf32x3 QK + tf32x1 PV on mma.sync.m16n8k8.
// BM=128, BN=64, 256 thr / 8 warps; warp = m16 x n64 stripe.
// SMEM (bytes): Qp 65536 | Kp 32768 | Vp 16384 | Pp 32768 = 147456.
//   Qp/Kp: uint4 per (k8, row, j=tg): {hi_c, hi_c+4, lo_c, lo_c+4}
//   Vp/Pp: uint2 per (kk8, n/row, tg): {tf32_k, tf32_k+4} (single-precision pass)
// grid = (S/128, BH)
// ---------------------------------------------------------------------------
#define ATT_SMEM 147456
#define KOFF 65536
#define VOFF 98304
#define POFF 114688

__global__ __launch_bounds__(256) void attn_kernel()
{
    extern __shared__ char smc[];
    uint32_t* Qw = (uint32_t*)smc;
    uint32_t* Kw = (uint32_t*)(smc + KOFF);
    uint32_t* Vw = (uint32_t*)(smc + VOFF);
    uint32_t* Pw = (uint32_t*)(smc + POFF);
    const uint4* Qu = (const uint4*)smc;
    const uint4* Ku = (const uint4*)(smc + KOFF);
    const uint2* Vu = (const uint2*)(smc + VOFF);
    const uint2* Pu = (const uint2*)(smc + POFF);

    const int tid = threadIdx.x;
    const int lane = tid & 31;
    const int warp = tid >> 5;
    const int g = lane >> 2;        // 0..7
    const int tg = lane & 3;        // 0..3
    const int rbase = warp * 16;    // warp's m16 stripe base row
    const int bh = blockIdx.y;
    const int q0 = blockIdx.x * 128;

    const float* Qg = g_Q + ((size_t)bh * S_ + q0) * D_;
    const float* Kg = g_K + (size_t)bh * S_ * D_;
    const float* Vg = g_V + (size_t)bh * S_ * D_;

    // ---- Q load + scale + split (once) ----
#pragma unroll
    for (int it = 0; it < 8; it++) {
        int slot = tid + it * 256;          // 0..2047 float4 slots
        int row = slot >> 4;                // 0..127
        int c4 = (slot & 15) * 4;
        float4 f = *(const float4*)(Qg + (size_t)row * D_ + c4);
        const float* fe = (const float*)&f;
#pragma unroll
        for (int j = 0; j < 4; j++) {
            int c = c4 + j;
            int k8 = c >> 3, w = (c >> 2) & 1, jj = c & 3;
            uint32_t hi, lo;
            split_tf(fe[j] * 0.125f, hi, lo);
            int idx = ((((k8 << 7) + row) * 4 + jj) << 2) + w;
            Qw[idx] = hi; Qw[idx + 2] = lo;
        }
    }

    float m0 = -1e30f, m1 = -1e30f, l0 = 0.f, l1 = 0.f;
    float oacc[8][4];
#pragma unroll
    for (int nf = 0; nf < 8; nf++)
#pragma unroll
        for (int c = 0; c < 4; c++) oacc[nf][c] = 0.f;

    // preload K/V tile 0 into regs
    float4 kf[4], vf[4];
#pragma unroll
    for (int it = 0; it < 4; it++) {
        int slot = tid + it * 256;          // 0..1023
        int row = slot >> 4;
        int c4 = (slot & 15) * 4;
        kf[it] = *(const float4*)(Kg + (size_t)row * D_ + c4);
        vf[it] = *(const float4*)(Vg + (size_t)row * D_ + c4);
    }

    for (int kb = 0; kb < 32; kb++) {
        // ---- split + store K (hi/lo) and V (single tf32) ----
#pragma unroll
        for (int it = 0; it < 4; it++) {
            int slot = tid + it * 256;
            int row = slot >> 4;            // key 0..63
            int c4 = (slot & 15) * 4;
            const float* ke = (const float*)&kf[it];
            const float* ve = (const float*)&vf[it];
#pragma unroll
            for (int j = 0; j < 4; j++) {
                int c = c4 + j;
                int k8 = c >> 3, w = (c >> 2) & 1, jj = c & 3;
                uint32_t hi, lo;
                split_tf(ke[j], hi, lo);
                int idx = ((((k8 << 6) + row) * 4 + jj) << 2) + w;
                Kw[idx] = hi; Kw[idx + 2] = lo;
            }
            {
                int kk8 = row >> 3, vtg = row & 3, half = (row >> 2) & 1;
#pragma unroll
                for (int j = 0; j < 4; j++) {
                    int d = c4 + j;
                    int idx = ((((kk8 << 6) + d) * 4 + vtg) << 1) + half;
                    Vw[idx] = f2tf(ve[j]);
                }
            }
        }
        __syncthreads();

        // issue next tile's loads early (latency hidden under QK MMAs)
        if (kb < 31) {
#pragma unroll
            for (int it = 0; it < 4; it++) {
                int slot = tid + it * 256;
                int row = slot >> 4;
                int c4 = (slot & 15) * 4;
                kf[it] = *(const float4*)(Kg + ((size_t)(kb + 1) * 64 + row) * D_ + c4);
                vf[it] = *(const float4*)(Vg + ((size_t)(kb + 1) * 64 + row) * D_ + c4);
            }
        }

        // ---- S = (Q/8) K^T  (3-pass tf32) ----
        float sacc[8][4];
#pragma unroll
        for (int nf = 0; nf < 8; nf++)
#pragma unroll
            for (int c = 0; c < 4; c++) sacc[nf][c] = 0.f;

#pragma unroll 2
        for (int k8 = 0; k8 < 8; k8++) {
            uint4 A0 = Qu[((k8 << 7) + rbase + g) * 4 + tg];
            uint4 A1 = Qu[((k8 << 7) + rbase + g + 8) * 4 + tg];
#pragma unroll
            for (int nf = 0; nf < 8; nf++) {
                uint4 Bv = Ku[((k8 << 6) + nf * 8 + g) * 4 + tg];
                mma8(sacc[nf], A0.x, A1.x, A0.y, A1.y, Bv.x, Bv.y);
                mma8(sacc[nf], A0.z, A1.z, A0.w, A1.w, Bv.x, Bv.y);
                mma8(sacc[nf], A0.x, A1.x, A0.y, A1.y, Bv.z, Bv.w);
            }
        }

        // ---- online softmax (rows rbase+g and rbase+g+8) ----
        float mx0 = -1e30f, mx1 = -1e30f;
#pragma unroll
        for (int nf = 0; nf < 8; nf++) {
            mx0 = fmaxf(mx0, fmaxf(sacc[nf][0], sacc[nf][1]));
            mx1 = fmaxf(mx1, fmaxf(sacc[nf][2], sacc[nf][3]));
        }
        mx0 = fmaxf(mx0, __shfl_xor_sync(0xffffffffu, mx0, 1));
        mx0 = fmaxf(mx0, __shfl_xor_sync(0xffffffffu, mx0, 2));
        mx1 = fmaxf(mx1, __shfl_xor_sync(0xffffffffu, mx1, 1));
        mx1 = fmaxf(mx1, __shfl_xor_sync(0xffffffffu, mx1, 2));
        float mn0 = fmaxf(m0, mx0), mn1 = fmaxf(m1, mx1);
        float corr0 = fast_exp(m0 - mn0), corr1 = fast_exp(m1 - mn1);
        m0 = mn0; m1 = mn1;

        const int rA = rbase + g, rB = rA + 8;
        float sum0 = 0.f, sum1 = 0.f;
#pragma unroll
        for (int nf = 0; nf < 8; nf++) {
            float p0 = fast_exp(sacc[nf][0] - mn0);
            float p1 = fast_exp(sacc[nf][1] - mn0);
            float p2 = fast_exp(sacc[nf][2] - mn1);
            float p3 = fast_exp(sacc[nf][3] - mn1);
            sum0 += p0 + p1; sum1 += p2 + p3;
            int cA = 2 * tg, cB = 2 * tg + 1;           // col within kk8=nf block
            int iA0 = ((((nf << 7) + rA) * 4 + (cA & 3)) << 1) + (cA >> 2);
            int iB0 = ((((nf << 7) + rA) * 4 + (cB & 3)) << 1) + (cB >> 2);
            int iA1 = ((((nf << 7) + rB) * 4 + (cA & 3)) << 1) + (cA >> 2);
            int iB1 = ((((nf << 7) + rB) * 4 + (cB & 3)) << 1) + (cB >> 2);
            Pw[iA0] = f2tf(p0); Pw[iB0] = f2tf(p1);
            Pw[iA1] = f2tf(p2); Pw[iB1] = f2tf(p3);
            oacc[nf][0] *= corr0; oacc[nf][1] *= corr0;
            oacc[nf][2] *= corr1; oacc[nf][3] *= corr1;
        }
        sum0 += __shfl_xor_sync(0xffffffffu, sum0, 1);
        sum0 += __shfl_xor_sync(0xffffffffu, sum0, 2);
        sum1 += __shfl_xor_sync(0xffffffffu, sum1, 1);
        sum1 += __shfl_xor_sync(0xffffffffu, sum1, 2);
        l0 = l0 * corr0 + sum0;
        l1 = l1 * corr1 + sum1;

        __syncwarp();   // P rows of this stripe written only by this warp

        // ---- O += P V  (1-pass tf32) ----
#pragma unroll 2
        for (int kk8 = 0; kk8 < 8; kk8++) {
            uint2 P0 = Pu[((kk8 << 7) + rbase + g) * 4 + tg];
            uint2 P1 = Pu[((kk8 << 7) + rbase + g + 8) * 4 + tg];
#pragma unroll
            for (int nf = 0; nf < 8; nf++) {
                uint2 Bv = Vu[((kk8 << 6) + nf * 8 + g) * 4 + tg];
                mma8(oacc[nf], P0.x, P1.x, P0.y, P1.y, Bv.x, Bv.y);
            }
        }
        __syncthreads();    // WAR: everyone done with Kp/Vp before next stores
    }

    // ---- epilogue ----
    float inv0 = 1.f / l0, inv1 = 1.f / l1;
    float* Cg = g_C + ((size_t)bh * S_ + q0) * D_;
    const int rA = rbase + g, rB = rA + 8;
#pragma unroll
    for (int nf = 0; nf < 8; nf++) {
        int col = nf * 8 + 2 * tg;
        *(float2*)(Cg + (size_t)rA * D_ + col) =
            make_float2(oacc[nf][0] * inv0, oacc[nf][1] * inv0);
        *(float2*)(Cg + (size_t)rB * D_ + col) =
            make_float2(oacc[nf][2] * inv1, oacc[nf][3] * inv1);
    }
}

// ---------------------------------------------------------------------------
// Output projection (FFMA, unchanged)
// ---------------------------------------------------------------------------
__global__ __launch_bounds__(256) void oproj_kernel(
    const float* __restrict__ Wo, const float* __restrict__ bo, float* __restrict__ out)
{
    __shared__ float As[16][132];
    __shared__ float Bs[16][64];

    const int m0 = blockIdx.x * 128;
    const int n0 = blockIdx.y * 64;
    const int tid = threadIdx.x;
    const int ng = tid & 15;
    const int mg = tid >> 4;
    const int b = m0 >> 11;
    const int sbase = m0 & (S_ - 1);

    float acc[8][4];
#pragma unroll
    for (int i = 0; i < 8; i++)
#pragma unroll
        for (int j = 0; j < 4; j++) acc[i][j] = 0.f;

    for (int k0 = 0; k0 < E_; k0 += 16) {
#pragma unroll
        for (int it = 0; it < 2; it++) {
            int i = tid + it * 256;
            int row = i >> 2;
            int c4 = (i & 3) * 4;
            int e = k0 + c4;
            int h = e >> 6;
            int dd = e & 63;
            float4 f = *(const float4*)(g_C +
                (((size_t)(b * H_ + h) * S_ + sbase + row) * D_ + dd));
            As[c4 + 0][row] = f.x; As[c4 + 1][row] = f.y;
            As[c4 + 2][row] = f.z; As[c4 + 3][row] = f.w;
        }
        {
            int r = tid >> 4, c4 = (tid & 15) * 4;
            *(float4*)&Bs[r][c4] = *(const float4*)(Wo + (size_t)(k0 + r) * E_ + n0 + c4);
        }
        __syncthreads();
#pragma unroll
        for (int kk = 0; kk < 16; kk++) {
            float4 a0 = *(float4*)&As[kk][mg * 8];
            float4 a1 = *(float4*)&As[kk][mg * 8 + 4];
            float4 b4 = *(float4*)&Bs[kk][ng * 4];
            float a[8] = {a0.x, a0.y, a0.z, a0.w, a1.x, a1.y, a1.z, a1.w};
            float bb[4] = {b4.x, b4.y, b4.z, b4.w};
#pragma unroll
            for (int i = 0; i < 8; i++)
#pragma unroll
                for (int j = 0; j < 4; j++) acc[i][j] += a[i] * bb[j];
        }
        __syncthreads();
    }

    float4 b4 = *(const float4*)(bo + n0 + ng * 4);
#pragma unroll
    for (int i = 0; i < 8; i++) {
        size_t row = (size_t)m0 + mg * 8 + i;
        float4 r;
        r.x = acc[i][0] + b4.x; r.y = acc[i][1] + b4.y;
        r.z = acc[i][2] + b4.z; r.w = acc[i][3] + b4.w;
        *(float4*)(out + row * E_ + n0 + ng * 4) = r;
    }
}

// ---------------------------------------------------------------------------
extern "C" void kernel_launch(void* const* d_in, const int* in_sizes, int n_in,
                              void* d_out, int out_size)
{
    const float* q  = (const float*)d_in[0];
    const float* k  = (const float*)d_in[1];
    const float* v  = (const float*)d_in[2];
    const float* Wq = (const float*)d_in[3];
    const float* Wk = (const float*)d_in[4];
    const float* Wv = (const float*)d_in[5];
    const float* bq = (const float*)d_in[6];
    const float* bk = (const float*)d_in[7];
    const float* bv = (const float*)d_in[8];
    const float* Wo = (const float*)d_in[9];
    const float* bo = (const float*)d_in[10];
    float* out = (float*)d_out;

    cudaFuncSetAttribute(attn_kernel, cudaFuncAttributeMaxDynamicSharedMemorySize, ATT_SMEM);

    proj_kernel<<<dim3(S_ / 128, BH_, 3), 256>>>(q, k, v, Wq, Wk, Wv, bq, bk, bv);
    attn_kernel<<<dim3(S_ / 128, BH_), 256, ATT_SMEM>>>();
    oproj_kernel<<<dim3((B_ * S_) / 128, E_ / 64), 256>>>(Wo, bo, out);
}